// round 6
// baseline (speedup 1.0000x reference)
#include <cuda_runtime.h>

// Fixed problem shape
#define B_   8
#define C_   64
#define H_   96
#define W_   96
#define O_   64
#define K_   9
#define HW_  (H_ * W_)        // 9216
#define Q_   HW_
#define CK_  (C_ * K_)        // 576

#define TILE 256              // output pixels per block
#define NE   (K_ * TILE)      // 2304 sampling entries
#define THREADS 256
#define NBLK (B_ * Q_ / TILE) // 288

#define CB      8             // channels per chunk
#define NCHUNK  (C_ / CB)     // 8
#define KSTEP   (CB * K_)     // 72 K-steps per chunk
#define BSP     268           // Bs row pitch (words): conflict-free, 16B-aligned rows

// Dynamic smem layout (bytes)
#define SMEM_IDX   0
#define SMEM_WT    (NE * 16)                      // 36864
#define SMEM_BS    (2 * NE * 16)                  // 73728
#define SMEM_AS    (SMEM_BS + KSTEP * BSP * 4)    // 150912
#define SMEM_TOTAL (SMEM_AS + KSTEP * O_ * 4)     // 169344

// Scratch: NHWC input + [ck][o] weights
__device__ float g_inT[(size_t)B_ * HW_ * C_];    // ~18.9 MB
__device__ float g_wT[CK_ * O_];

// ---------------------------------------------------------------------------
// Kernel 1: NCHW -> NHWC input transpose (+ weight transpose in last block)
// ---------------------------------------------------------------------------
__global__ __launch_bounds__(256) void transpose_kernel(
    const float* __restrict__ in,   // [B][C][H][W]
    const float* __restrict__ wgt)  // [O][C*K]
{
    int blk = blockIdx.x;
    if (blk == B_ * (HW_ / 32)) {          // weight transpose block
        for (int i = threadIdx.x; i < CK_ * O_; i += 256) {
            int ck = i >> 6, o = i & 63;
            g_wT[i] = wgt[o * CK_ + ck];
        }
        return;
    }
    __shared__ float s[64][33];
    int b   = blk / (HW_ / 32);
    int hw0 = (blk % (HW_ / 32)) * 32;
    for (int i = threadIdx.x; i < 64 * 32; i += 256) {
        int c = i >> 5, hw = i & 31;
        s[c][hw] = in[((size_t)(b * C_ + c)) * HW_ + hw0 + hw];
    }
    __syncthreads();
    for (int i = threadIdx.x; i < 64 * 32; i += 256) {
        int hw = i >> 6, c = i & 63;
        g_inT[((size_t)(b * HW_ + hw0 + hw)) * C_ + c] = s[c][hw];
    }
}

// ---------------------------------------------------------------------------
// Kernel 2: fused deformable gather (NHWC, vectorized) + register-tiled GEMM
// ---------------------------------------------------------------------------
__global__ __launch_bounds__(256, 1) void dcn_fused_kernel(
    const float* __restrict__ offset,  // [B][2K][Ho][Wo]
    const float* __restrict__ mask,    // [B][K][Ho][Wo]
    const float* __restrict__ bias,    // [O]
    float* __restrict__ out)           // [B][O][Ho][Wo]
{
    extern __shared__ char smem_raw[];
    int4*   s_idx = (int4*)(smem_raw + SMEM_IDX);     // [NE]
    float4* s_wt  = (float4*)(smem_raw + SMEM_WT);    // [NE]
    float*  Bs    = (float*)(smem_raw + SMEM_BS);     // [KSTEP][BSP]
    float*  As    = (float*)(smem_raw + SMEM_AS);     // [KSTEP][64]

    const int tid   = threadIdx.x;
    const int bq    = blockIdx.x;
    const int b     = bq / (Q_ / TILE);               // /36
    const int qbase = (bq % (Q_ / TILE)) * TILE;

    // ---------------- Phase 1: sampling coords/weights (channel-invariant) -
    for (int e = tid; e < NE; e += THREADS) {
        int k = e >> 8;                 // e / TILE
        int n = e & (TILE - 1);
        int q = qbase + n;
        int ho = q / W_;
        int wo = q - ho * W_;
        int ky = k / 3;
        int kx = k - ky * 3;

        float offy = offset[((size_t)(b * 2 * K_ + 2 * k)) * Q_ + q];
        float offx = offset[((size_t)(b * 2 * K_ + 2 * k + 1)) * Q_ + q];
        float m    = mask[((size_t)(b * K_ + k)) * Q_ + q];

        float y = (float)(ho - 1 + ky) + offy;
        float x = (float)(wo - 1 + kx) + offx;

        float y0f = floorf(y), x0f = floorf(x);
        int y0 = (int)y0f, x0 = (int)x0f;
        int y1 = y0 + 1,   x1 = x0 + 1;
        float wy = y - y0f, wx = x - x0f;

        float vy0 = (y0 >= 0 && y0 < H_) ? 1.0f : 0.0f;
        float vy1 = (y1 >= 0 && y1 < H_) ? 1.0f : 0.0f;
        float vx0 = (x0 >= 0 && x0 < W_) ? 1.0f : 0.0f;
        float vx1 = (x1 >= 0 && x1 < W_) ? 1.0f : 0.0f;

        float w00 = (1.0f - wy) * (1.0f - wx) * m * vy0 * vx0;
        float w01 = (1.0f - wy) * wx          * m * vy0 * vx1;
        float w10 = wy          * (1.0f - wx) * m * vy1 * vx0;
        float w11 = wy          * wx          * m * vy1 * vx1;

        int y0c = min(max(y0, 0), H_ - 1);
        int y1c = min(max(y1, 0), H_ - 1);
        int x0c = min(max(x0, 0), W_ - 1);
        int x1c = min(max(x1, 0), W_ - 1);

        s_idx[e] = make_int4(y0c * W_ + x0c, y0c * W_ + x1c,
                             y1c * W_ + x0c, y1c * W_ + x1c);
        s_wt[e]  = make_float4(w00, w01, w10, w11);
    }

    // ---------------- GEMM thread mapping ----------------------------------
    const int trow = tid >> 5;            // m0 = trow*8 (uniform per warp)
    const int tcol = tid & 31;
    const int m0   = trow * 8;
    const int n0a  = 4 * tcol;            // first float4 of n
    const int n0b  = 4 * tcol + 128;      // second float4 of n

    // acc[i][j]: i = m (8 rows), j = n-pair: 0,1 -> n0a block ; 2,3 -> n0b block
    unsigned long long acc[8][4];
    #pragma unroll
    for (int i = 0; i < 8; ++i)
        #pragma unroll
        for (int j = 0; j < 4; ++j) acc[i][j] = 0ULL;

    const float* Tb = g_inT + (size_t)b * HW_ * C_;

    for (int chunk = 0; chunk < NCHUNK; ++chunk) {
        __syncthreads();   // previous GEMM finished reading As/Bs

        // As: flat copy of rows [chunk*72, chunk*72+72) of g_wT
        {
            const float* src = g_wT + chunk * (KSTEP * O_);
            for (int i = tid; i < KSTEP * O_; i += THREADS)
                As[i] = src[i];
        }

        // Gather: 2 threads per entry, 4 channels (float4) each
        {
            const float* cb = Tb + chunk * CB;   // + half*4 below
            for (int it = tid; it < 2 * NE; it += THREADS) {
                int e    = it >> 1;
                int half = it & 1;
                int4   ii = s_idx[e];
                float4 ww = s_wt[e];
                const float* cbh = cb + half * 4;

                float4 p00 = *(const float4*)(cbh + (size_t)ii.x * C_);
                float4 p01 = *(const float4*)(cbh + (size_t)ii.y * C_);
                float4 p10 = *(const float4*)(cbh + (size_t)ii.z * C_);
                float4 p11 = *(const float4*)(cbh + (size_t)ii.w * C_);

                float4 v;
                v.x = ww.x * p00.x + ww.y * p01.x + ww.z * p10.x + ww.w * p11.x;
                v.y = ww.x * p00.y + ww.y * p01.y + ww.z * p10.y + ww.w * p11.y;
                v.z = ww.x * p00.z + ww.y * p01.z + ww.z * p10.z + ww.w * p11.z;
                v.w = ww.x * p00.w + ww.y * p01.w + ww.z * p10.w + ww.w * p11.w;

                int k = e >> 8;
                int n = e & (TILE - 1);
                int r0 = (half * 4) * K_ + k;         // row = lc*9 + k
                Bs[(r0     ) * BSP + n] = v.x;
                Bs[(r0 +  9) * BSP + n] = v.y;
                Bs[(r0 + 18) * BSP + n] = v.z;
                Bs[(r0 + 27) * BSP + n] = v.w;
            }
        }

        __syncthreads();

        // GEMM: 72 K-steps over this chunk
        #pragma unroll 8
        for (int kk = 0; kk < KSTEP; ++kk) {
            // A: warp-uniform broadcast loads
            float4 a04 = *(const float4*)&As[kk * O_ + m0];
            float4 a48 = *(const float4*)&As[kk * O_ + m0 + 4];
            unsigned long long ad[8];
            asm("mov.b64 %0, {%1, %1};" : "=l"(ad[0]) : "f"(a04.x));
            asm("mov.b64 %0, {%1, %1};" : "=l"(ad[1]) : "f"(a04.y));
            asm("mov.b64 %0, {%1, %1};" : "=l"(ad[2]) : "f"(a04.z));
            asm("mov.b64 %0, {%1, %1};" : "=l"(ad[3]) : "f"(a04.w));
            asm("mov.b64 %0, {%1, %1};" : "=l"(ad[4]) : "f"(a48.x));
            asm("mov.b64 %0, {%1, %1};" : "=l"(ad[5]) : "f"(a48.y));
            asm("mov.b64 %0, {%1, %1};" : "=l"(ad[6]) : "f"(a48.z));
            asm("mov.b64 %0, {%1, %1};" : "=l"(ad[7]) : "f"(a48.w));

            // B: pairs along n come directly from 64-bit lanes of float4 loads
            ulonglong2 bpa = *(const ulonglong2*)&Bs[kk * BSP + n0a];
            ulonglong2 bpb = *(const ulonglong2*)&Bs[kk * BSP + n0b];

            #pragma unroll
            for (int i = 0; i < 8; ++i) {
                asm("fma.rn.f32x2 %0, %1, %2, %0;" : "+l"(acc[i][0]) : "l"(ad[i]), "l"(bpa.x));
                asm("fma.rn.f32x2 %0, %1, %2, %0;" : "+l"(acc[i][1]) : "l"(ad[i]), "l"(bpa.y));
                asm("fma.rn.f32x2 %0, %1, %2, %0;" : "+l"(acc[i][2]) : "l"(ad[i]), "l"(bpb.x));
                asm("fma.rn.f32x2 %0, %1, %2, %0;" : "+l"(acc[i][3]) : "l"(ad[i]), "l"(bpb.y));
            }
        }
    }

    // ---------------- Epilogue --------------------------------------------
    #pragma unroll
    for (int i = 0; i < 8; ++i) {
        int o = m0 + i;
        float bi = bias[o];
        float f0, f1, f2, f3;
        asm("mov.b64 {%0, %1}, %2;" : "=f"(f0), "=f"(f1) : "l"(acc[i][0]));
        asm("mov.b64 {%0, %1}, %2;" : "=f"(f2), "=f"(f3) : "l"(acc[i][1]));
        float4 va = make_float4(f0 + bi, f1 + bi, f2 + bi, f3 + bi);
        asm("mov.b64 {%0, %1}, %2;" : "=f"(f0), "=f"(f1) : "l"(acc[i][2]));
        asm("mov.b64 {%0, %1}, %2;" : "=f"(f2), "=f"(f3) : "l"(acc[i][3]));
        float4 vb = make_float4(f0 + bi, f1 + bi, f2 + bi, f3 + bi);
        float* op = &out[((size_t)(b * O_ + o)) * Q_ + qbase];
        *(float4*)&op[n0a] = va;
        *(float4*)&op[n0b] = vb;
    }
}

// ---------------------------------------------------------------------------
extern "C" void kernel_launch(void* const* d_in, const int* in_sizes, int n_in,
                              void* d_out, int out_size)
{
    const float* input  = (const float*)d_in[0];  // [8,64,96,96]
    const float* offset = (const float*)d_in[1];  // [8,18,96,96]
    const float* mask   = (const float*)d_in[2];  // [8,9,96,96]
    const float* weight = (const float*)d_in[3];  // [64,64,3,3]
    const float* bias   = (const float*)d_in[4];  // [64]
    float* out = (float*)d_out;                   // [8,64,96,96]

    static int smem_set = 0;
    if (!smem_set) {
        cudaFuncSetAttribute(dcn_fused_kernel,
                             cudaFuncAttributeMaxDynamicSharedMemorySize,
                             SMEM_TOTAL);
        smem_set = 1;
    }

    transpose_kernel<<<B_ * (HW_ / 32) + 1, 256>>>(input, weight);
    dcn_fused_kernel<<<NBLK, THREADS, SMEM_TOTAL>>>(offset, mask, bias, out);
}

// round 8
// speedup vs baseline: 3.6712x; 3.6712x over previous
#include <cuda_runtime.h>
#include <cstdint>

// ---------------------------------------------------------------- shapes
#define B_   8
#define C_   64
#define H_   96
#define W_   96
#define O_   64
#define K_   9
#define HW_  (H_ * W_)        // 9216
#define Q_   HW_

#define TILE_PX 128
#define NTILES  (B_ * Q_ / TILE_PX)   // 576
#define THREADS 256
#define PITCH   36                    // smem row pitch in 32-bit words (32 data + 4 pad)

// ---------------------------------------------------------------- smem map (bytes)
#define SM_BIAS  0                       // float[64]
#define SM_IDX   256                     // int4[128]
#define SM_WT    2304                    // float4[128]
#define SM_AHI   4352                    // uint32[128*36] = 18432 B
#define SM_ALO   22784
#define SM_BHI   41216                   // uint32[64*36]  = 9216 B
#define SM_BLO   50432
#define SM_TOTAL 59648

// ---------------------------------------------------------------- global scratch
__device__ float    g_inT[(size_t)B_ * HW_ * C_];   // NHWC input (~18.9 MB)
__device__ uint32_t g_wBh[K_ * O_ * PITCH];         // bf16x2 weight words (hi), [tap][o][w]
__device__ uint32_t g_wBl[K_ * O_ * PITCH];         // (lo)

// ---------------------------------------------------------------- helpers
__device__ __forceinline__ uint32_t pack_bf16x2(float lo, float hi) {
    uint32_t r;
    asm("cvt.rn.bf16x2.f32 %0, %1, %2;" : "=r"(r) : "f"(hi), "f"(lo));
    return r;
}

// split a float pair into bf16x2 hi word + bf16x2 residual word
__device__ __forceinline__ void split_pair(float v0, float v1,
                                           uint32_t& hw, uint32_t& lw) {
    hw = pack_bf16x2(v0, v1);
    float h0 = __uint_as_float(hw << 16);
    float h1 = __uint_as_float(hw & 0xFFFF0000u);
    lw = pack_bf16x2(v0 - h0, v1 - h1);
}

#define MMA_BF16(d, a0, a1, a2, a3, b0, b1)                                   \
    asm volatile(                                                             \
        "mma.sync.aligned.m16n8k16.row.col.f32.bf16.bf16.f32 "                \
        "{%0,%1,%2,%3}, {%4,%5,%6,%7}, {%8,%9}, {%0,%1,%2,%3};"               \
        : "+f"((d)[0]), "+f"((d)[1]), "+f"((d)[2]), "+f"((d)[3])              \
        : "r"(a0), "r"(a1), "r"(a2), "r"(a3), "r"(b0), "r"(b1))

// ---------------------------------------------------------------------------
// Prepass: NCHW -> NHWC input transpose + weight hi/lo bf16 split into
// col-major [tap][o][kw] word images (kw = channel pair index).
// ---------------------------------------------------------------------------
__global__ __launch_bounds__(256) void prep_kernel(
    const float* __restrict__ in,    // [B][C][H][W]
    const float* __restrict__ wgt)   // [O][C][3][3]
{
    int blk = blockIdx.x;
    if (blk >= B_ * (HW_ / 32)) {                 // 9 weight blocks, one per tap
        int tap = blk - B_ * (HW_ / 32);
        for (int i = threadIdx.x; i < O_ * 32; i += 256) {
            int o = i >> 5;
            int w = i & 31;
            float w0 = wgt[o * 576 + (2 * w)     * 9 + tap];
            float w1 = wgt[o * 576 + (2 * w + 1) * 9 + tap];
            uint32_t hw, lw;
            split_pair(w0, w1, hw, lw);
            g_wBh[(tap * O_ + o) * PITCH + w] = hw;
            g_wBl[(tap * O_ + o) * PITCH + w] = lw;
        }
        return;
    }
    __shared__ float s[64][33];
    int b   = blk / (HW_ / 32);
    int hw0 = (blk % (HW_ / 32)) * 32;
    for (int i = threadIdx.x; i < 64 * 32; i += 256) {
        int c = i >> 5, hw = i & 31;
        s[c][hw] = in[((size_t)(b * C_ + c)) * HW_ + hw0 + hw];
    }
    __syncthreads();
    for (int i = threadIdx.x; i < 64 * 32; i += 256) {
        int hw = i >> 6, c = i & 63;
        g_inT[((size_t)(b * HW_ + hw0 + hw)) * C_ + c] = s[c][hw];
    }
}

// ---------------------------------------------------------------------------
// Main fused kernel: block = 128 output pixels of one batch image.
// Loop over 9 taps: bilinear NHWC gather (64 ch) -> bf16 hi/lo smem tiles ->
// mma.sync m16n8k16 bf16, 3 split terms, fp32 accumulators held in registers.
// ---------------------------------------------------------------------------
__global__ __launch_bounds__(256, 2) void dcn_mma_kernel(
    const float* __restrict__ offset,  // [B][18][96][96]
    const float* __restrict__ mask,    // [B][9][96][96]
    const float* __restrict__ bias,    // [64]
    float* __restrict__ out)           // [B][64][96][96]
{
    extern __shared__ char smem[];
    float*    s_bias = (float*)(smem + SM_BIAS);
    int4*     s_idx  = (int4*)(smem + SM_IDX);
    float4*   s_wt   = (float4*)(smem + SM_WT);
    uint32_t* Ah     = (uint32_t*)(smem + SM_AHI);
    uint32_t* Al     = (uint32_t*)(smem + SM_ALO);
    uint32_t* Bh     = (uint32_t*)(smem + SM_BHI);
    uint32_t* Bl     = (uint32_t*)(smem + SM_BLO);

    const int tid   = threadIdx.x;
    const int lane  = tid & 31;
    const int wid   = tid >> 5;
    const int b     = blockIdx.x / (Q_ / TILE_PX);       // /72
    const int qbase = (blockIdx.x % (Q_ / TILE_PX)) * TILE_PX;

    if (tid < 64) s_bias[tid] = bias[tid];

    const float* Tb = g_inT + (size_t)b * HW_ * C_;

    // fragment accumulators: 8 n-tiles x 4 regs
    float acc[8][4];
    #pragma unroll
    for (int nt = 0; nt < 8; ++nt)
        #pragma unroll
        for (int j = 0; j < 4; ++j) acc[nt][j] = 0.0f;

    // per-thread fragment smem offsets (words)
    const int m0    = wid * 16;
    const int aoff  = (m0 + (lane >> 2)) * PITCH + (lane & 3);
    const int boff  = (lane >> 2) * PITCH + (lane & 3);

    for (int tap = 0; tap < K_; ++tap) {
        __syncthreads();   // prev tap: all LDS reads of A/B/coords finished

        // ---- coords for this tap (128 px) -------------------------------
        if (tid < TILE_PX) {
            int q  = qbase + tid;
            int ho = q / W_;
            int wo = q - ho * W_;
            int ky = tap / 3;
            int kx = tap - ky * 3;

            float offy = offset[((size_t)(b * 2 * K_ + 2 * tap)) * Q_ + q];
            float offx = offset[((size_t)(b * 2 * K_ + 2 * tap + 1)) * Q_ + q];
            float m    = mask[((size_t)(b * K_ + tap)) * Q_ + q];

            float y = (float)(ho - 1 + ky) + offy;
            float x = (float)(wo - 1 + kx) + offx;
            float y0f = floorf(y), x0f = floorf(x);
            int y0 = (int)y0f, x0 = (int)x0f;
            int y1 = y0 + 1,   x1 = x0 + 1;
            float wy = y - y0f, wx = x - x0f;

            float vy0 = (y0 >= 0 && y0 < H_) ? 1.0f : 0.0f;
            float vy1 = (y1 >= 0 && y1 < H_) ? 1.0f : 0.0f;
            float vx0 = (x0 >= 0 && x0 < W_) ? 1.0f : 0.0f;
            float vx1 = (x1 >= 0 && x1 < W_) ? 1.0f : 0.0f;

            float w00 = (1.0f - wy) * (1.0f - wx) * m * vy0 * vx0;
            float w01 = (1.0f - wy) * wx          * m * vy0 * vx1;
            float w10 = wy          * (1.0f - wx) * m * vy1 * vx0;
            float w11 = wy          * wx          * m * vy1 * vx1;

            int y0c = min(max(y0, 0), H_ - 1);
            int y1c = min(max(y1, 0), H_ - 1);
            int x0c = min(max(x0, 0), W_ - 1);
            int x1c = min(max(x1, 0), W_ - 1);

            s_idx[tid] = make_int4(y0c * W_ + x0c, y0c * W_ + x1c,
                                   y1c * W_ + x0c, y1c * W_ + x1c);
            s_wt[tid]  = make_float4(w00, w01, w10, w11);
        }

        // ---- stage B (weight) tiles: straight uint4 copy ----------------
        {
            const uint4* srcH = (const uint4*)(g_wBh + tap * O_ * PITCH);
            const uint4* srcL = (const uint4*)(g_wBl + tap * O_ * PITCH);
            uint4* dH = (uint4*)Bh;
            uint4* dL = (uint4*)Bl;
            #pragma unroll
            for (int i = tid; i < O_ * PITCH / 4; i += THREADS) {
                dH[i] = srcH[i];
                dL[i] = srcL[i];
            }
        }

        __syncthreads();   // coords visible

        // ---- gather A tile: 2048 tasks = (px, 4-channel group) ----------
        #pragma unroll
        for (int iter = 0; iter < 8; ++iter) {
            int it = tid + iter * 256;
            int px = it >> 4;
            int c4 = it & 15;
            int4   ii = s_idx[px];
            float4 ww = s_wt[px];
            const float* cb = Tb + c4 * 4;

            float4 p00 = *(const float4*)(cb + (size_t)ii.x * C_);
            float4 p01 = *(const float4*)(cb + (size_t)ii.y * C_);
            float4 p10 = *(const float4*)(cb + (size_t)ii.z * C_);
            float4 p11 = *(const float4*)(cb + (size_t)ii.w * C_);

            float v0 = ww.x*p00.x + ww.y*p01.x + ww.z*p10.x + ww.w*p11.x;
            float v1 = ww.x*p00.y + ww.y*p01.y + ww.z*p10.y + ww.w*p11.y;
            float v2 = ww.x*p00.z + ww.y*p01.z + ww.z*p10.z + ww.w*p11.z;
            float v3 = ww.x*p00.w + ww.y*p01.w + ww.z*p10.w + ww.w*p11.w;

            uint32_t h01, l01, h23, l23;
            split_pair(v0, v1, h01, l01);
            split_pair(v2, v3, h23, l23);

            int o = px * PITCH + 2 * c4;
            Ah[o] = h01;  Ah[o + 1] = h23;
            Al[o] = l01;  Al[o + 1] = l23;
        }

        __syncthreads();   // A + B tiles ready

        // ---- MMA: 4 k-steps (16 ch each) x 8 n-tiles x 3 terms ----------
        #pragma unroll
        for (int ks = 0; ks < 4; ++ks) {
            const int kb = ks * 8;
            uint32_t ah0 = Ah[aoff + kb];
            uint32_t ah1 = Ah[aoff + 8 * PITCH + kb];
            uint32_t ah2 = Ah[aoff + kb + 4];
            uint32_t ah3 = Ah[aoff + 8 * PITCH + kb + 4];
            uint32_t al0 = Al[aoff + kb];
            uint32_t al1 = Al[aoff + 8 * PITCH + kb];
            uint32_t al2 = Al[aoff + kb + 4];
            uint32_t al3 = Al[aoff + 8 * PITCH + kb + 4];

            #pragma unroll
            for (int nt = 0; nt < 8; ++nt) {
                int bo = boff + nt * 8 * PITCH + kb;
                uint32_t bh0 = Bh[bo], bh1 = Bh[bo + 4];
                uint32_t bl0 = Bl[bo], bl1 = Bl[bo + 4];
                MMA_BF16(acc[nt], ah0, ah1, ah2, ah3, bh0, bh1);
                MMA_BF16(acc[nt], ah0, ah1, ah2, ah3, bl0, bl1);
                MMA_BF16(acc[nt], al0, al1, al2, al3, bh0, bh1);
            }
        }
    }

    // ---- epilogue: D frag (row=px, col=o) -> out[b][o][q] + bias ---------
    float* ob = out + (size_t)b * O_ * Q_;
    const int px0 = qbase + m0 + (lane >> 2);
    #pragma unroll
    for (int nt = 0; nt < 8; ++nt) {
        int o0 = nt * 8 + 2 * (lane & 3);
        int o1 = o0 + 1;
        float b0 = s_bias[o0];
        float b1 = s_bias[o1];
        ob[(size_t)o0 * Q_ + px0]     = acc[nt][0] + b0;
        ob[(size_t)o1 * Q_ + px0]     = acc[nt][1] + b1;
        ob[(size_t)o0 * Q_ + px0 + 8] = acc[nt][2] + b0;
        ob[(size_t)o1 * Q_ + px0 + 8] = acc[nt][3] + b1;
    }
}

// ---------------------------------------------------------------------------
extern "C" void kernel_launch(void* const* d_in, const int* in_sizes, int n_in,
                              void* d_out, int out_size)
{
    const float* input  = (const float*)d_in[0];  // [8,64,96,96]
    const float* offset = (const float*)d_in[1];  // [8,18,96,96]
    const float* mask   = (const float*)d_in[2];  // [8,9,96,96]
    const float* weight = (const float*)d_in[3];  // [64,64,3,3]
    const float* bias   = (const float*)d_in[4];  // [64]
    float* out = (float*)d_out;                   // [8,64,96,96]

    static int init_done = 0;
    if (!init_done) {
        cudaFuncSetAttribute(dcn_mma_kernel,
                             cudaFuncAttributeMaxDynamicSharedMemorySize,
                             SM_TOTAL);
        init_done = 1;
    }

    prep_kernel<<<B_ * (HW_ / 32) + K_, 256>>>(input, weight);
    dcn_mma_kernel<<<NTILES, THREADS, SM_TOTAL>>>(offset, mask, bias, out);
}

// round 9
// speedup vs baseline: 3.7370x; 1.0179x over previous
#include <cuda_runtime.h>
#include <cstdint>

// ---------------------------------------------------------------- shapes
#define B_   8
#define C_   64
#define H_   96
#define W_   96
#define O_   64
#define K_   9
#define HW_  (H_ * W_)        // 9216
#define Q_   HW_

#define TILE_PX 128
#define NTILES  (B_ * Q_ / TILE_PX)   // 576
#define THREADS 256
#define PITCH   36                    // smem row pitch in words (32 data + 4 pad)
#define PITCHB  (PITCH * 4)           // 144 bytes

// ---------------------------------------------------------------- smem map (bytes)
#define SM_BIAS  0                        // float[64]
#define SM_IDX   256                      // int4[9*128]   = 18432
#define SM_WT    18688                    // float4[9*128] = 18432
#define SM_AHI   37120                    // uint32[128*36] = 18432
#define SM_ALO   55552
#define SM_BHI   73984                    // uint32[64*36]  = 9216
#define SM_BLO   83200
#define SM_TOTAL 92416

// ---------------------------------------------------------------- global scratch
__device__ float    g_inT[(size_t)B_ * HW_ * C_];   // NHWC input (~18.9 MB)
__device__ uint32_t g_wBh[K_ * O_ * PITCH];         // bf16x2 weight words (hi)
__device__ uint32_t g_wBl[K_ * O_ * PITCH];         // (lo)

// ---------------------------------------------------------------- helpers
__device__ __forceinline__ uint32_t smem_u32(const void* p) {
    uint32_t a;
    asm("{ .reg .u64 t; cvta.to.shared.u64 t, %1; cvt.u32.u64 %0, t; }"
        : "=r"(a) : "l"(p));
    return a;
}

__device__ __forceinline__ uint32_t pack_bf16x2(float lo, float hi) {
    uint32_t r;
    asm("cvt.rn.bf16x2.f32 %0, %1, %2;" : "=r"(r) : "f"(hi), "f"(lo));
    return r;
}

__device__ __forceinline__ void split_pair(float v0, float v1,
                                           uint32_t& hw, uint32_t& lw) {
    hw = pack_bf16x2(v0, v1);
    float h0 = __uint_as_float(hw << 16);
    float h1 = __uint_as_float(hw & 0xFFFF0000u);
    lw = pack_bf16x2(v0 - h0, v1 - h1);
}

#define MMA_BF16(d, a0, a1, a2, a3, b0, b1)                                   \
    asm volatile(                                                             \
        "mma.sync.aligned.m16n8k16.row.col.f32.bf16.bf16.f32 "                \
        "{%0,%1,%2,%3}, {%4,%5,%6,%7}, {%8,%9}, {%0,%1,%2,%3};"               \
        : "+f"((d)[0]), "+f"((d)[1]), "+f"((d)[2]), "+f"((d)[3])              \
        : "r"(a0), "r"(a1), "r"(a2), "r"(a3), "r"(b0), "r"(b1))

#define LDMX4(r0, r1, r2, r3, addr)                                           \
    asm volatile(                                                             \
        "ldmatrix.sync.aligned.m8n8.x4.shared.b16 {%0,%1,%2,%3}, [%4];"       \
        : "=r"(r0), "=r"(r1), "=r"(r2), "=r"(r3) : "r"(addr))

// ---------------------------------------------------------------------------
// Prepass: NCHW -> NHWC input transpose + weight hi/lo bf16 split,
// layout [tap][o][kw] (kw = channel-pair word), pitch 36.
// ---------------------------------------------------------------------------
__global__ __launch_bounds__(256) void prep_kernel(
    const float* __restrict__ in,    // [B][C][H][W]
    const float* __restrict__ wgt)   // [O][C][3][3]
{
    int blk = blockIdx.x;
    if (blk >= B_ * (HW_ / 32)) {
        int tap = blk - B_ * (HW_ / 32);
        for (int i = threadIdx.x; i < O_ * 32; i += 256) {
            int o = i >> 5;
            int w = i & 31;
            float w0 = wgt[o * 576 + (2 * w)     * 9 + tap];
            float w1 = wgt[o * 576 + (2 * w + 1) * 9 + tap];
            uint32_t hw, lw;
            split_pair(w0, w1, hw, lw);
            g_wBh[(tap * O_ + o) * PITCH + w] = hw;
            g_wBl[(tap * O_ + o) * PITCH + w] = lw;
        }
        return;
    }
    __shared__ float s[64][33];
    int b   = blk / (HW_ / 32);
    int hw0 = (blk % (HW_ / 32)) * 32;
    for (int i = threadIdx.x; i < 64 * 32; i += 256) {
        int c = i >> 5, hw = i & 31;
        s[c][hw] = in[((size_t)(b * C_ + c)) * HW_ + hw0 + hw];
    }
    __syncthreads();
    for (int i = threadIdx.x; i < 64 * 32; i += 256) {
        int hw = i >> 6, c = i & 63;
        g_inT[((size_t)(b * HW_ + hw0 + hw)) * C_ + c] = s[c][hw];
    }
}

// ---------------------------------------------------------------------------
// Main fused kernel.
// ---------------------------------------------------------------------------
__global__ __launch_bounds__(256, 2) void dcn_mma_kernel(
    const float* __restrict__ offset,  // [B][18][96][96]
    const float* __restrict__ mask,    // [B][9][96][96]
    const float* __restrict__ bias,    // [64]
    float* __restrict__ out)           // [B][64][96][96]
{
    extern __shared__ char smem[];
    float*    s_bias = (float*)(smem + SM_BIAS);
    int4*     s_idx  = (int4*)(smem + SM_IDX);
    float4*   s_wt   = (float4*)(smem + SM_WT);
    uint32_t* Ah     = (uint32_t*)(smem + SM_AHI);
    uint32_t* Al     = (uint32_t*)(smem + SM_ALO);

    const uint32_t sb = smem_u32(smem);
    const int tid   = threadIdx.x;
    const int lane  = tid & 31;
    const int wid   = tid >> 5;
    const int b     = blockIdx.x / (Q_ / TILE_PX);       // /72
    const int qbase = (blockIdx.x % (Q_ / TILE_PX)) * TILE_PX;

    if (tid < 64) s_bias[tid] = bias[tid];

    const float* Tb = g_inT + (size_t)b * HW_ * C_;

    // ---- Phase 0: coords for ALL 9 taps (1152 tasks) ---------------------
    for (int e = tid; e < K_ * TILE_PX; e += THREADS) {
        int tap = e >> 7;
        int px  = e & 127;
        int q  = qbase + px;
        int ho = q / W_;
        int wo = q - ho * W_;
        int ky = tap / 3;
        int kx = tap - ky * 3;

        float offy = offset[((size_t)(b * 2 * K_ + 2 * tap)) * Q_ + q];
        float offx = offset[((size_t)(b * 2 * K_ + 2 * tap + 1)) * Q_ + q];
        float m    = mask[((size_t)(b * K_ + tap)) * Q_ + q];

        float y = (float)(ho - 1 + ky) + offy;
        float x = (float)(wo - 1 + kx) + offx;
        float y0f = floorf(y), x0f = floorf(x);
        int y0 = (int)y0f, x0 = (int)x0f;
        int y1 = y0 + 1,   x1 = x0 + 1;
        float wy = y - y0f, wx = x - x0f;

        float vy0 = (y0 >= 0 && y0 < H_) ? 1.0f : 0.0f;
        float vy1 = (y1 >= 0 && y1 < H_) ? 1.0f : 0.0f;
        float vx0 = (x0 >= 0 && x0 < W_) ? 1.0f : 0.0f;
        float vx1 = (x1 >= 0 && x1 < W_) ? 1.0f : 0.0f;

        float w00 = (1.0f - wy) * (1.0f - wx) * m * vy0 * vx0;
        float w01 = (1.0f - wy) * wx          * m * vy0 * vx1;
        float w10 = wy          * (1.0f - wx) * m * vy1 * vx0;
        float w11 = wy          * wx          * m * vy1 * vx1;

        int y0c = min(max(y0, 0), H_ - 1);
        int y1c = min(max(y1, 0), H_ - 1);
        int x0c = min(max(x0, 0), W_ - 1);
        int x1c = min(max(x1, 0), W_ - 1);

        s_idx[e] = make_int4(y0c * W_ + x0c, y0c * W_ + x1c,
                             y1c * W_ + x0c, y1c * W_ + x1c);
        s_wt[e]  = make_float4(w00, w01, w10, w11);
    }

    // fragment accumulators: 8 n-tiles x 4 regs
    float acc[8][4];
    #pragma unroll
    for (int nt = 0; nt < 8; ++nt)
        #pragma unroll
        for (int j = 0; j < 4; ++j) acc[nt][j] = 0.0f;

    // per-thread ldmatrix row addressing
    const int m0     = wid * 16;
    const int lrow   = (lane & 7) + 8 * ((lane >> 3) & 1);   // row within 16
    const int lchunk = (lane >> 4);                          // 16B chunk (k 0-7 / 8-15)
    const uint32_t aAddrH = sb + SM_AHI + (m0 + lrow) * PITCHB + lchunk * 16;
    const uint32_t aAddrL = sb + SM_ALO + (m0 + lrow) * PITCHB + lchunk * 16;
    const uint32_t bRowOff = lrow * PITCHB + lchunk * 16;

    for (int tap = 0; tap < K_; ++tap) {
        __syncthreads();   // coords ready (tap 0) / prev-tap LDS reads done

        // ---- stage B (weight) tiles: straight uint4 copy ----------------
        {
            const uint4* srcH = (const uint4*)(g_wBh + tap * O_ * PITCH);
            const uint4* srcL = (const uint4*)(g_wBl + tap * O_ * PITCH);
            uint4* dH = (uint4*)(smem + SM_BHI);
            uint4* dL = (uint4*)(smem + SM_BLO);
            for (int i = tid; i < O_ * PITCH / 4; i += THREADS) {
                dH[i] = srcH[i];
                dL[i] = srcL[i];
            }
        }

        // ---- gather A tile: 2048 tasks = (px, 4-channel group) ----------
        #pragma unroll
        for (int iter = 0; iter < 8; ++iter) {
            int it = tid + iter * 256;
            int px = it >> 4;
            int c4 = it & 15;
            int4   ii = s_idx[tap * TILE_PX + px];
            float4 ww = s_wt[tap * TILE_PX + px];
            const float* cb = Tb + c4 * 4;

            float4 p00 = *(const float4*)(cb + (size_t)ii.x * C_);
            float4 p01 = *(const float4*)(cb + (size_t)ii.y * C_);
            float4 p10 = *(const float4*)(cb + (size_t)ii.z * C_);
            float4 p11 = *(const float4*)(cb + (size_t)ii.w * C_);

            float v0 = ww.x*p00.x + ww.y*p01.x + ww.z*p10.x + ww.w*p11.x;
            float v1 = ww.x*p00.y + ww.y*p01.y + ww.z*p10.y + ww.w*p11.y;
            float v2 = ww.x*p00.z + ww.y*p01.z + ww.z*p10.z + ww.w*p11.z;
            float v3 = ww.x*p00.w + ww.y*p01.w + ww.z*p10.w + ww.w*p11.w;

            uint32_t h01, l01, h23, l23;
            split_pair(v0, v1, h01, l01);
            split_pair(v2, v3, h23, l23);

            int o = px * PITCH + 2 * c4;
            *(uint2*)&Ah[o] = make_uint2(h01, h23);
            *(uint2*)&Al[o] = make_uint2(l01, l23);
        }

        __syncthreads();   // A + B tiles ready

        // ---- MMA: 4 k-steps x (2 A-ldm + 8 B-ldm + 24 MMA) --------------
        #pragma unroll
        for (int ks = 0; ks < 4; ++ks) {
            const int kb = ks * 32;   // bytes

            uint32_t ah0, ah1, ah2, ah3, al0, al1, al2, al3;
            LDMX4(ah0, ah1, ah2, ah3, aAddrH + kb);
            LDMX4(al0, al1, al2, al3, aAddrL + kb);

            #pragma unroll
            for (int p = 0; p < 4; ++p) {
                uint32_t bbase = p * 16 * PITCHB + bRowOff + kb;
                uint32_t bh0a, bh0b, bh1a, bh1b;
                uint32_t bl0a, bl0b, bl1a, bl1b;
                LDMX4(bh0a, bh0b, bh1a, bh1b, sb + SM_BHI + bbase);
                LDMX4(bl0a, bl0b, bl1a, bl1b, sb + SM_BLO + bbase);

                MMA_BF16(acc[2*p],     ah0, ah1, ah2, ah3, bh0a, bh1a);
                MMA_BF16(acc[2*p],     ah0, ah1, ah2, ah3, bl0a, bl1a);
                MMA_BF16(acc[2*p],     al0, al1, al2, al3, bh0a, bh1a);
                MMA_BF16(acc[2*p + 1], ah0, ah1, ah2, ah3, bh0b, bh1b);
                MMA_BF16(acc[2*p + 1], ah0, ah1, ah2, ah3, bl0b, bl1b);
                MMA_BF16(acc[2*p + 1], al0, al1, al2, al3, bh0b, bh1b);
            }
        }
    }

    // ---- epilogue: D frag (row=px, col=o) -> out[b][o][q] + bias ---------
    float* ob = out + (size_t)b * O_ * Q_;
    const int px0 = qbase + m0 + (lane >> 2);
    #pragma unroll
    for (int nt = 0; nt < 8; ++nt) {
        int o0 = nt * 8 + 2 * (lane & 3);
        int o1 = o0 + 1;
        float b0 = s_bias[o0];
        float b1 = s_bias[o1];
        ob[(size_t)o0 * Q_ + px0]     = acc[nt][0] + b0;
        ob[(size_t)o1 * Q_ + px0]     = acc[nt][1] + b1;
        ob[(size_t)o0 * Q_ + px0 + 8] = acc[nt][2] + b0;
        ob[(size_t)o1 * Q_ + px0 + 8] = acc[nt][3] + b1;
    }
}

// ---------------------------------------------------------------------------
extern "C" void kernel_launch(void* const* d_in, const int* in_sizes, int n_in,
                              void* d_out, int out_size)
{
    const float* input  = (const float*)d_in[0];  // [8,64,96,96]
    const float* offset = (const float*)d_in[1];  // [8,18,96,96]
    const float* mask   = (const float*)d_in[2];  // [8,9,96,96]
    const float* weight = (const float*)d_in[3];  // [64,64,3,3]
    const float* bias   = (const float*)d_in[4];  // [64]
    float* out = (float*)d_out;                   // [8,64,96,96]

    static int init_done = 0;
    if (!init_done) {
        cudaFuncSetAttribute(dcn_mma_kernel,
                             cudaFuncAttributeMaxDynamicSharedMemorySize,
                             SM_TOTAL);
        init_done = 1;
    }

    prep_kernel<<<B_ * (HW_ / 32) + K_, 256>>>(input, weight);
    dcn_mma_kernel<<<NTILES, THREADS, SM_TOTAL>>>(offset, mask, bias, out);
}